// round 4
// baseline (speedup 1.0000x reference)
#include <cuda_runtime.h>
#include <cstdint>

#define NN   50000
#define EE   800000
#define FIN  64
#define HH   128
#define GG   16

// ---------------- device scratch (static allocation only) ----------------
__device__ float g_dinv[NN];                 // deg -> dinv (in place)
__device__ float g_norm[EE];                 // per-edge symmetric norm
__device__ float g_hw  [(size_t)NN * HH];    // h @ W
__device__ float g_agg [(size_t)NN * HH];    // scatter-add accumulator
__device__ float g_h   [(size_t)NN * HH];    // activations between layers
__device__ float g_pool[GG * HH];
__device__ float g_cnt [GG];

// ---------------- helpers ----------------
__device__ __forceinline__ void red_add_v4(float* addr, float4 v) {
    asm volatile("red.global.add.v4.f32 [%0], {%1,%2,%3,%4};"
                 :: "l"(addr), "f"(v.x), "f"(v.y), "f"(v.z), "f"(v.w)
                 : "memory");
}

// ---------------- norm precompute ----------------
__global__ void deg_init_kernel() {
    int i = blockIdx.x * blockDim.x + threadIdx.x;
    if (i < NN) g_dinv[i] = 1.0f;            // self-loop contributes 1 to degree
}

__global__ void deg_acc_kernel(const int* __restrict__ dst) {
    int e = blockIdx.x * blockDim.x + threadIdx.x;
    if (e < EE) atomicAdd(&g_dinv[dst[e]], 1.0f);
}

__global__ void dinv_kernel() {
    int i = blockIdx.x * blockDim.x + threadIdx.x;
    if (i < NN) g_dinv[i] = rsqrtf(g_dinv[i]);   // deg >= 1 always
}

__global__ void norm_kernel(const int* __restrict__ src, const int* __restrict__ dst) {
    int e = blockIdx.x * blockDim.x + threadIdx.x;
    if (e < EE) g_norm[e] = g_dinv[src[e]] * g_dinv[dst[e]];
}

// ---------------- zero fill ----------------
__global__ void zero_kernel(float* __restrict__ p, int n4) {   // n4 = count of float4
    int i = blockIdx.x * blockDim.x + threadIdx.x;
    if (i < n4) reinterpret_cast<float4*>(p)[i] = make_float4(0.f, 0.f, 0.f, 0.f);
}

// ---------------- SGEMM: C[M,128] = A[M,K] @ B[K,128] ----------------
// BM=128, BN=128, BK=16, TM=TN=8, 256 threads
__global__ __launch_bounds__(256) void gemm_kernel(
    const float* __restrict__ A, const float* __restrict__ B,
    float* __restrict__ C, int M, int K)
{
    __shared__ float As[16][128];
    __shared__ float Bs[16][128];

    const int tid = threadIdx.x;
    const int tr  = tid >> 4;          // 0..15
    const int tc  = tid & 15;          // 0..15
    const int block_row = blockIdx.x * 128;

    float acc[8][8];
#pragma unroll
    for (int m = 0; m < 8; m++)
#pragma unroll
        for (int n = 0; n < 8; n++) acc[m][n] = 0.f;

    for (int k0 = 0; k0 < K; k0 += 16) {
        // load A tile (128 x 16) = 512 float4, 2 per thread, store transposed
#pragma unroll
        for (int i = 0; i < 2; i++) {
            int f   = tid + i * 256;
            int row = f >> 2;
            int c4  = (f & 3) * 4;
            int grow = block_row + row;
            float4 v = make_float4(0.f, 0.f, 0.f, 0.f);
            if (grow < M)
                v = *reinterpret_cast<const float4*>(A + (size_t)grow * K + k0 + c4);
            As[c4 + 0][row] = v.x;
            As[c4 + 1][row] = v.y;
            As[c4 + 2][row] = v.z;
            As[c4 + 3][row] = v.w;
        }
        // load B tile (16 x 128) = 512 float4, 2 per thread
#pragma unroll
        for (int i = 0; i < 2; i++) {
            int f   = tid + i * 256;
            int row = f >> 5;
            int c4  = (f & 31) * 4;
            float4 v = *reinterpret_cast<const float4*>(B + (size_t)(k0 + row) * 128 + c4);
            *reinterpret_cast<float4*>(&Bs[row][c4]) = v;
        }
        __syncthreads();

#pragma unroll
        for (int k = 0; k < 16; k++) {
            float a[8], b[8];
#pragma unroll
            for (int m = 0; m < 8; m++) a[m] = As[k][tr * 8 + m];
#pragma unroll
            for (int n = 0; n < 8; n++) b[n] = Bs[k][tc * 8 + n];
#pragma unroll
            for (int m = 0; m < 8; m++)
#pragma unroll
                for (int n = 0; n < 8; n++) acc[m][n] = fmaf(a[m], b[n], acc[m][n]);
        }
        __syncthreads();
    }

    // writeback
#pragma unroll
    for (int m = 0; m < 8; m++) {
        int grow = block_row + tr * 8 + m;
        if (grow < M) {
#pragma unroll
            for (int n4 = 0; n4 < 2; n4++) {
                float4 v = make_float4(acc[m][n4 * 4 + 0], acc[m][n4 * 4 + 1],
                                       acc[m][n4 * 4 + 2], acc[m][n4 * 4 + 3]);
                *reinterpret_cast<float4*>(C + (size_t)grow * 128 + tc * 8 + n4 * 4) = v;
            }
        }
    }
}

// ---------------- edge messages: agg[dst] += hw[src] * norm ----------------
// one warp per edge, one float4 per lane (128 floats = 512B coalesced)
__global__ __launch_bounds__(256) void message_kernel(
    const int* __restrict__ src, const int* __restrict__ dst)
{
    int gid  = blockIdx.x * blockDim.x + threadIdx.x;
    int e    = gid >> 5;
    int lane = gid & 31;
    if (e >= EE) return;
    int   s  = __ldg(&src[e]);
    int   d  = __ldg(&dst[e]);
    float nv = __ldg(&g_norm[e]);
    float4 v = *reinterpret_cast<const float4*>(&g_hw[(size_t)s * 128 + lane * 4]);
    v.x *= nv; v.y *= nv; v.z *= nv; v.w *= nv;
    red_add_v4(&g_agg[(size_t)d * 128 + lane * 4], v);
}

// ---------------- epilogue: h = [relu](agg + hw * dinv^2 + b) ----------------
__global__ void epilogue_kernel(const float* __restrict__ bias, int do_relu) {
    int gid  = blockIdx.x * blockDim.x + threadIdx.x;   // over NN*32 float4 chunks
    if (gid >= NN * 32) return;
    int i = gid >> 5;
    int c = gid & 31;
    float dn = g_dinv[i];
    float sn = dn * dn;
    float4 a = reinterpret_cast<const float4*>(g_agg)[gid];
    float4 h = reinterpret_cast<const float4*>(g_hw)[gid];
    float4 b = *reinterpret_cast<const float4*>(bias + c * 4);
    float4 r;
    r.x = a.x + h.x * sn + b.x;
    r.y = a.y + h.y * sn + b.y;
    r.z = a.z + h.z * sn + b.z;
    r.w = a.w + h.w * sn + b.w;
    if (do_relu) {
        r.x = fmaxf(r.x, 0.f); r.y = fmaxf(r.y, 0.f);
        r.z = fmaxf(r.z, 0.f); r.w = fmaxf(r.w, 0.f);
    }
    reinterpret_cast<float4*>(g_h)[gid] = r;
}

// ---------------- pooling: pooled[g] += h[i]; cnt[g] += 1 ----------------
__global__ __launch_bounds__(256) void pool_kernel(const int* __restrict__ batch) {
    int gid  = blockIdx.x * blockDim.x + threadIdx.x;
    int i    = gid >> 5;
    int lane = gid & 31;
    if (i >= NN) return;
    int g = __ldg(&batch[i]);
    float4 v = *reinterpret_cast<const float4*>(&g_h[(size_t)i * 128 + lane * 4]);
    red_add_v4(&g_pool[g * 128 + lane * 4], v);
    if (lane == 0) atomicAdd(&g_cnt[g], 1.0f);
}

// ---------------- MLP head (single block) ----------------
__global__ __launch_bounds__(256) void mlp_kernel(
    const float* __restrict__ lw1, const float* __restrict__ lb1,
    const float* __restrict__ lw2, const float* __restrict__ lb2,
    float* __restrict__ out)
{
    __shared__ float p[GG][HH];
    __shared__ float mid[GG][64];
    int t = threadIdx.x;

    for (int i = t; i < GG * HH; i += 256) {
        int g = i / HH;
        p[g][i % HH] = g_pool[i] / fmaxf(g_cnt[g], 1.0f);
    }
    __syncthreads();

    for (int i = t; i < GG * 64; i += 256) {
        int g = i / 64, j = i % 64;
        float s = lb1[j];
#pragma unroll 8
        for (int k = 0; k < 128; k++) s = fmaf(p[g][k], lw1[k * 64 + j], s);
        mid[g][j] = fmaxf(s, 0.f);
    }
    __syncthreads();

    if (t < GG * 2) {
        int g = t >> 1, c = t & 1;
        float s = lb2[c];
#pragma unroll 8
        for (int k = 0; k < 64; k++) s = fmaf(mid[g][k], lw2[k * 2 + c], s);
        out[g * 2 + c] = s;
    }
}

// ---------------- host launcher ----------------
extern "C" void kernel_launch(void* const* d_in, const int* in_sizes, int n_in,
                              void* d_out, int out_size)
{
    const float* x    = (const float*)d_in[0];
    const int*   ei   = (const int*)  d_in[1];
    const int*   batch= (const int*)  d_in[2];
    const float* W1 = (const float*)d_in[3];  const float* b1 = (const float*)d_in[4];
    const float* W2 = (const float*)d_in[5];  const float* b2 = (const float*)d_in[6];
    const float* W3 = (const float*)d_in[7];  const float* b3 = (const float*)d_in[8];
    const float* W4 = (const float*)d_in[9];  const float* b4 = (const float*)d_in[10];
    const float* lw1= (const float*)d_in[11]; const float* lb1= (const float*)d_in[12];
    const float* lw2= (const float*)d_in[13]; const float* lb2= (const float*)d_in[14];
    float* out = (float*)d_out;

    const int* src = ei;        // edge_index[0]
    const int* dst = ei + EE;   // edge_index[1]

    float *p_hw, *p_agg, *p_h, *p_pool, *p_cnt;
    cudaGetSymbolAddress((void**)&p_hw,   g_hw);
    cudaGetSymbolAddress((void**)&p_agg,  g_agg);
    cudaGetSymbolAddress((void**)&p_h,    g_h);
    cudaGetSymbolAddress((void**)&p_pool, g_pool);
    cudaGetSymbolAddress((void**)&p_cnt,  g_cnt);

    // ---- normalization coefficients ----
    deg_init_kernel<<<(NN + 255) / 256, 256>>>();
    deg_acc_kernel <<<(EE + 255) / 256, 256>>>(dst);
    dinv_kernel    <<<(NN + 255) / 256, 256>>>();
    norm_kernel    <<<(EE + 255) / 256, 256>>>(src, dst);

    const int gemm_blocks = (NN + 127) / 128;
    const int zero4       = NN * 32;                         // float4 count of agg
    const int msg_blocks  = (EE * 32 + 255) / 256;
    const int epi_blocks  = (NN * 32 + 255) / 256;

    struct Layer { const float* W; const float* b; int K; int relu; };
    const Layer layers[4] = {
        { W1, b1, FIN, 1 }, { W2, b2, HH, 1 }, { W3, b3, HH, 1 }, { W4, b4, HH, 0 }
    };

    const float* h_in = x;
    for (int L = 0; L < 4; L++) {
        gemm_kernel   <<<gemm_blocks, 256>>>(h_in, layers[L].W, p_hw, NN, layers[L].K);
        zero_kernel   <<<(zero4 + 255) / 256, 256>>>(p_agg, zero4);
        message_kernel<<<msg_blocks, 256>>>(src, dst);
        epilogue_kernel<<<epi_blocks, 256>>>(layers[L].b, layers[L].relu);
        h_in = p_h;
    }

    // ---- pooling + head ----
    zero_kernel<<<(GG * HH / 4 + 255) / 256, 256>>>(p_pool, GG * HH / 4);
    zero_kernel<<<1, 256>>>(p_cnt, GG / 4);
    pool_kernel<<<(NN * 32 + 255) / 256, 256>>>(batch);
    mlp_kernel <<<1, 256>>>(lw1, lb1, lw2, lb2, out);
}

// round 5
// speedup vs baseline: 1.2155x; 1.2155x over previous
#include <cuda_runtime.h>
#include <cstdint>

#define NN   50000
#define EE   800000
#define FIN  64
#define HH   128
#define GG   16

// ---------------- device scratch (static allocation only) ----------------
__device__ int   g_cnt  [NN];                 // degree counts -> CSR cursor
__device__ int   g_rowptr[NN + 1];
__device__ int2  g_edge [EE];                 // {src, norm bits} sorted by dst
__device__ float g_dinv [NN];
__device__ float g_hw   [(size_t)NN * HH];    // h @ W
__device__ float g_h    [(size_t)NN * HH];    // activations between layers
__device__ float g_pool [GG * HH];
__device__ float g_gcnt [GG];

// ---------------- helpers ----------------
__device__ __forceinline__ void red_add_v4(float* addr, float4 v) {
    asm volatile("red.global.add.v4.f32 [%0], {%1,%2,%3,%4};"
                 :: "l"(addr), "f"(v.x), "f"(v.y), "f"(v.z), "f"(v.w)
                 : "memory");
}

// ---------------- precompute: zero counters / pool ----------------
__global__ void init_kernel() {
    int i = blockIdx.x * blockDim.x + threadIdx.x;
    if (i < NN) g_cnt[i] = 0;
    if (i < GG * HH) g_pool[i] = 0.f;
    if (i < GG) g_gcnt[i] = 0.f;
}

__global__ void gcnt_kernel(const int* __restrict__ batch) {
    int i = blockIdx.x * blockDim.x + threadIdx.x;
    if (i < NN) atomicAdd(&g_gcnt[batch[i]], 1.0f);
}

__global__ void deg_kernel(const int* __restrict__ dst) {
    int e = blockIdx.x * blockDim.x + threadIdx.x;
    if (e < EE) atomicAdd(&g_cnt[dst[e]], 1);
}

// single-block exclusive scan of degrees -> rowptr, cursor, dinv
__global__ __launch_bounds__(1024) void scan_kernel() {
    __shared__ int sm[1024];
    const int CH = (NN + 1023) / 1024;            // 49
    int t   = threadIdx.x;
    int beg = t * CH;
    int end = min(beg + CH, NN);
    int s = 0;
    for (int i = beg; i < end; i++) s += g_cnt[i];
    sm[t] = s;
    __syncthreads();
    if (t == 0) {
        int run = 0;
        for (int j = 0; j < 1024; j++) { int v = sm[j]; sm[j] = run; run += v; }
    }
    __syncthreads();
    int off = sm[t];
    for (int i = beg; i < end; i++) {
        int v = g_cnt[i];
        g_rowptr[i] = off;
        g_cnt[i]    = off;                        // cursor for fill
        g_dinv[i]   = rsqrtf((float)(v + 1));     // +1 self loop
        off += v;
    }
    if (t == 0) g_rowptr[NN] = EE;
}

__global__ void fill_kernel(const int* __restrict__ src, const int* __restrict__ dst) {
    int e = blockIdx.x * blockDim.x + threadIdx.x;
    if (e >= EE) return;
    int   s  = src[e];
    int   d  = dst[e];
    float nv = g_dinv[s] * g_dinv[d];
    int   p  = atomicAdd(&g_cnt[d], 1);
    g_edge[p] = make_int2(s, __float_as_int(nv));
}

// ---------------- SGEMM: C[M,128] = A[M,K] @ B[K,128] ----------------
__global__ __launch_bounds__(256) void gemm_kernel(
    const float* __restrict__ A, const float* __restrict__ B,
    float* __restrict__ C, int M, int K)
{
    __shared__ float As[16][128];
    __shared__ float Bs[16][128];

    const int tid = threadIdx.x;
    const int tr  = tid >> 4;
    const int tc  = tid & 15;
    const int block_row = blockIdx.x * 128;

    float acc[8][8];
#pragma unroll
    for (int m = 0; m < 8; m++)
#pragma unroll
        for (int n = 0; n < 8; n++) acc[m][n] = 0.f;

    for (int k0 = 0; k0 < K; k0 += 16) {
#pragma unroll
        for (int i = 0; i < 2; i++) {
            int f   = tid + i * 256;
            int row = f >> 2;
            int c4  = (f & 3) * 4;
            int grow = block_row + row;
            float4 v = make_float4(0.f, 0.f, 0.f, 0.f);
            if (grow < M)
                v = *reinterpret_cast<const float4*>(A + (size_t)grow * K + k0 + c4);
            As[c4 + 0][row] = v.x;
            As[c4 + 1][row] = v.y;
            As[c4 + 2][row] = v.z;
            As[c4 + 3][row] = v.w;
        }
#pragma unroll
        for (int i = 0; i < 2; i++) {
            int f   = tid + i * 256;
            int row = f >> 5;
            int c4  = (f & 31) * 4;
            float4 v = *reinterpret_cast<const float4*>(B + (size_t)(k0 + row) * 128 + c4);
            *reinterpret_cast<float4*>(&Bs[row][c4]) = v;
        }
        __syncthreads();

#pragma unroll
        for (int k = 0; k < 16; k++) {
            float a[8], b[8];
#pragma unroll
            for (int m = 0; m < 8; m++) a[m] = As[k][tr * 8 + m];
#pragma unroll
            for (int n = 0; n < 8; n++) b[n] = Bs[k][tc * 8 + n];
#pragma unroll
            for (int m = 0; m < 8; m++)
#pragma unroll
                for (int n = 0; n < 8; n++) acc[m][n] = fmaf(a[m], b[n], acc[m][n]);
        }
        __syncthreads();
    }

#pragma unroll
    for (int m = 0; m < 8; m++) {
        int grow = block_row + tr * 8 + m;
        if (grow < M) {
#pragma unroll
            for (int n4 = 0; n4 < 2; n4++) {
                float4 v = make_float4(acc[m][n4 * 4 + 0], acc[m][n4 * 4 + 1],
                                       acc[m][n4 * 4 + 2], acc[m][n4 * 4 + 3]);
                *reinterpret_cast<float4*>(C + (size_t)grow * 128 + tc * 8 + n4 * 4) = v;
            }
        }
    }
}

// ---------------- fused aggregate + self-loop + bias + relu (+pool) ----------
// one warp per destination node; register accumulation, no atomics
__global__ __launch_bounds__(256) void msg_fused_kernel(
    const float* __restrict__ bias, int do_relu, int do_pool,
    const int* __restrict__ batch)
{
    int gid  = blockIdx.x * blockDim.x + threadIdx.x;
    int i    = gid >> 5;
    int lane = gid & 31;
    if (i >= NN) return;

    int beg = __ldg(&g_rowptr[i]);
    int end = __ldg(&g_rowptr[i + 1]);

    float4 acc = make_float4(0.f, 0.f, 0.f, 0.f);
    int e = beg;
    for (; e + 1 < end; e += 2) {
        int2 p0 = __ldg(&g_edge[e]);
        int2 p1 = __ldg(&g_edge[e + 1]);
        float n0 = __int_as_float(p0.y);
        float n1 = __int_as_float(p1.y);
        float4 v0 = *reinterpret_cast<const float4*>(&g_hw[(size_t)p0.x * 128 + lane * 4]);
        float4 v1 = *reinterpret_cast<const float4*>(&g_hw[(size_t)p1.x * 128 + lane * 4]);
        acc.x = fmaf(v0.x, n0, acc.x); acc.y = fmaf(v0.y, n0, acc.y);
        acc.z = fmaf(v0.z, n0, acc.z); acc.w = fmaf(v0.w, n0, acc.w);
        acc.x = fmaf(v1.x, n1, acc.x); acc.y = fmaf(v1.y, n1, acc.y);
        acc.z = fmaf(v1.z, n1, acc.z); acc.w = fmaf(v1.w, n1, acc.w);
    }
    if (e < end) {
        int2 p0 = __ldg(&g_edge[e]);
        float n0 = __int_as_float(p0.y);
        float4 v0 = *reinterpret_cast<const float4*>(&g_hw[(size_t)p0.x * 128 + lane * 4]);
        acc.x = fmaf(v0.x, n0, acc.x); acc.y = fmaf(v0.y, n0, acc.y);
        acc.z = fmaf(v0.z, n0, acc.z); acc.w = fmaf(v0.w, n0, acc.w);
    }

    float dn = __ldg(&g_dinv[i]);
    float sn = dn * dn;                            // self-loop norm
    float4 hs = *reinterpret_cast<const float4*>(&g_hw[(size_t)i * 128 + lane * 4]);
    float4 b  = *reinterpret_cast<const float4*>(bias + lane * 4);

    float4 r;
    r.x = fmaf(hs.x, sn, acc.x) + b.x;
    r.y = fmaf(hs.y, sn, acc.y) + b.y;
    r.z = fmaf(hs.z, sn, acc.z) + b.z;
    r.w = fmaf(hs.w, sn, acc.w) + b.w;
    if (do_relu) {
        r.x = fmaxf(r.x, 0.f); r.y = fmaxf(r.y, 0.f);
        r.z = fmaxf(r.z, 0.f); r.w = fmaxf(r.w, 0.f);
    }
    *reinterpret_cast<float4*>(&g_h[(size_t)i * 128 + lane * 4]) = r;

    if (do_pool) {
        int g = __ldg(&batch[i]);
        red_add_v4(&g_pool[g * 128 + lane * 4], r);
    }
}

// ---------------- MLP head (single block) ----------------
__global__ __launch_bounds__(256) void mlp_kernel(
    const float* __restrict__ lw1, const float* __restrict__ lb1,
    const float* __restrict__ lw2, const float* __restrict__ lb2,
    float* __restrict__ out)
{
    __shared__ float p[GG][HH];
    __shared__ float mid[GG][64];
    int t = threadIdx.x;

    for (int i = t; i < GG * HH; i += 256) {
        int g = i / HH;
        p[g][i % HH] = g_pool[i] / fmaxf(g_gcnt[g], 1.0f);
    }
    __syncthreads();

    for (int i = t; i < GG * 64; i += 256) {
        int g = i / 64, j = i % 64;
        float s = lb1[j];
#pragma unroll 8
        for (int k = 0; k < 128; k++) s = fmaf(p[g][k], lw1[k * 64 + j], s);
        mid[g][j] = fmaxf(s, 0.f);
    }
    __syncthreads();

    if (t < GG * 2) {
        int g = t >> 1, c = t & 1;
        float s = lb2[c];
#pragma unroll 8
        for (int k = 0; k < 64; k++) s = fmaf(mid[g][k], lw2[k * 2 + c], s);
        out[g * 2 + c] = s;
    }
}

// ---------------- host launcher ----------------
extern "C" void kernel_launch(void* const* d_in, const int* in_sizes, int n_in,
                              void* d_out, int out_size)
{
    const float* x    = (const float*)d_in[0];
    const int*   ei   = (const int*)  d_in[1];
    const int*   batch= (const int*)  d_in[2];
    const float* W1 = (const float*)d_in[3];  const float* b1 = (const float*)d_in[4];
    const float* W2 = (const float*)d_in[5];  const float* b2 = (const float*)d_in[6];
    const float* W3 = (const float*)d_in[7];  const float* b3 = (const float*)d_in[8];
    const float* W4 = (const float*)d_in[9];  const float* b4 = (const float*)d_in[10];
    const float* lw1= (const float*)d_in[11]; const float* lb1= (const float*)d_in[12];
    const float* lw2= (const float*)d_in[13]; const float* lb2= (const float*)d_in[14];
    float* out = (float*)d_out;

    const int* src = ei;        // edge_index[0]  (message source)
    const int* dst = ei + EE;   // edge_index[1]  (aggregation target)

    float *p_hw, *p_h;
    cudaGetSymbolAddress((void**)&p_hw, g_hw);
    cudaGetSymbolAddress((void**)&p_h,  g_h);

    // ---- CSR build + normalization (once, reused by all 4 layers) ----
    init_kernel<<<(NN + 255) / 256, 256>>>();
    gcnt_kernel<<<(NN + 255) / 256, 256>>>(batch);
    deg_kernel <<<(EE + 255) / 256, 256>>>(dst);
    scan_kernel<<<1, 1024>>>();
    fill_kernel<<<(EE + 255) / 256, 256>>>(src, dst);

    const int gemm_blocks = (NN + 127) / 128;
    const int msg_blocks  = (NN * 32 + 255) / 256;

    struct Layer { const float* W; const float* b; int K; int relu; int pool; };
    const Layer layers[4] = {
        { W1, b1, FIN, 1, 0 }, { W2, b2, HH, 1, 0 },
        { W3, b3, HH,  1, 0 }, { W4, b4, HH, 0, 1 }
    };

    const float* h_in = x;
    for (int L = 0; L < 4; L++) {
        gemm_kernel     <<<gemm_blocks, 256>>>(h_in, layers[L].W, p_hw, NN, layers[L].K);
        msg_fused_kernel<<<msg_blocks, 256>>>(layers[L].b, layers[L].relu,
                                              layers[L].pool, batch);
        h_in = p_h;
    }

    mlp_kernel<<<1, 256>>>(lw1, lb1, lw2, lb2, out);
}